// round 1
// baseline (speedup 1.0000x reference)
#include <cuda_runtime.h>
#include <math.h>

#define NN 50000
#define NE 800000
#define FH 192          // HEADS*HID
#define HID 64
#define LOG2E 1.4426950408889634f

// ---------------- scratch (static device globals; no allocation) ----------------
__device__ __align__(16) float g_feat[NN * FH];   // 38.4 MB
__device__ __align__(16) float g_h[NN * HID];     // 12.8 MB
__device__ float g_el[NN * 3];
__device__ float g_er[NN * 3];
__device__ int   g_cnt[NN];
__device__ int   g_rp[NN + 1];
__device__ int   g_wp[NN];
__device__ int   g_col[NE];

__device__ __forceinline__ float lrelu(float x, float s) { return x > 0.f ? x : s * x; }

// ---------------- CSR build (sort edges by dst) ----------------
__global__ void k_zero() {
    int i = blockIdx.x * blockDim.x + threadIdx.x;
    if (i < NN) g_cnt[i] = 0;
}

__global__ void k_hist(const int* __restrict__ dst) {
    int e = blockIdx.x * blockDim.x + threadIdx.x;
    if (e < NE) atomicAdd(&g_cnt[dst[e]], 1);
}

// single-block exclusive scan over 50000 counts (warp-shfl based)
__global__ void k_scan() {
    __shared__ int wsum[32];
    __shared__ int carry;
    int tid = threadIdx.x, lane = tid & 31, wid = tid >> 5;
    if (tid == 0) carry = 0;
    __syncthreads();
    for (int base = 0; base < NN; base += 1024) {
        int i = base + tid;
        int v = (i < NN) ? g_cnt[i] : 0;
        int x = v;
        #pragma unroll
        for (int o = 1; o < 32; o <<= 1) {
            int t = __shfl_up_sync(0xffffffffu, x, o);
            if (lane >= o) x += t;
        }
        if (lane == 31) wsum[wid] = x;
        __syncthreads();
        if (wid == 0) {
            int y = wsum[lane];
            #pragma unroll
            for (int o = 1; o < 32; o <<= 1) {
                int t = __shfl_up_sync(0xffffffffu, y, o);
                if (lane >= o) y += t;
            }
            wsum[lane] = y;
        }
        __syncthreads();
        int pre = carry + (wid ? wsum[wid - 1] : 0) + x - v;  // exclusive prefix
        if (i < NN) { g_rp[i] = pre; g_wp[i] = pre; }
        __syncthreads();
        if (tid == 0) carry += wsum[31];
        __syncthreads();
    }
    if (threadIdx.x == 0) g_rp[NN] = carry;
}

__global__ void k_scatter(const int* __restrict__ src, const int* __restrict__ dst) {
    int e = blockIdx.x * blockDim.x + threadIdx.x;
    if (e < NE) {
        int p = atomicAdd(&g_wp[dst[e]], 1);
        g_col[p] = src[e];
    }
}

// ---------------- feat = A @ W  (A: [NN,K], W: [K,192], C = g_feat) ----------------
#define BM 128
#define BN 96
#define BK 16
__global__ __launch_bounds__(256) void k_gemm(const float* __restrict__ Ain,
                                              const float* __restrict__ W, int K) {
    const float* A = Ain ? Ain : g_h;
    __shared__ float As[BM][BK + 4];   // padded rows (20 floats, 16B-aligned stride)
    __shared__ float Bs[BK][BN];
    int tid = threadIdx.x;
    int tx = tid & 15;       // 16 column groups of 6
    int ty = tid >> 4;       // 16 row groups of 8
    int m0 = blockIdx.x * BM;
    int n0 = blockIdx.y * BN;

    float acc[8][6];
    #pragma unroll
    for (int i = 0; i < 8; i++)
        #pragma unroll
        for (int j = 0; j < 6; j++) acc[i][j] = 0.f;

    for (int k0 = 0; k0 < K; k0 += BK) {
        // A tile: 128x16 = 512 float4, 2 per thread
        #pragma unroll
        for (int i = 0; i < 2; i++) {
            int idx = tid + i * 256;
            int m = idx >> 2, kq = idx & 3;
            int gm = m0 + m;
            float4 v = make_float4(0.f, 0.f, 0.f, 0.f);
            if (gm < NN) v = *reinterpret_cast<const float4*>(&A[gm * K + k0 + kq * 4]);
            As[m][kq * 4 + 0] = v.x; As[m][kq * 4 + 1] = v.y;
            As[m][kq * 4 + 2] = v.z; As[m][kq * 4 + 3] = v.w;
        }
        // B tile: 16x96 = 1536 floats, 6 per thread
        #pragma unroll
        for (int i = 0; i < 6; i++) {
            int idx = tid + i * 256;
            int k = idx / BN, c = idx % BN;
            Bs[k][c] = W[(k0 + k) * FH + n0 + c];
        }
        __syncthreads();
        #pragma unroll
        for (int kk = 0; kk < BK; kk++) {
            float a[8], b[6];
            #pragma unroll
            for (int i = 0; i < 8; i++) a[i] = As[ty * 8 + i][kk];
            #pragma unroll
            for (int j = 0; j < 6; j++) b[j] = Bs[kk][tx * 6 + j];
            #pragma unroll
            for (int i = 0; i < 8; i++)
                #pragma unroll
                for (int j = 0; j < 6; j++) acc[i][j] += a[i] * b[j];
        }
        __syncthreads();
    }
    #pragma unroll
    for (int i = 0; i < 8; i++) {
        int gm = m0 + ty * 8 + i;
        if (gm < NN) {
            #pragma unroll
            for (int j = 0; j < 6; j++)
                g_feat[gm * FH + n0 + tx * 6 + j] = acc[i][j];
        }
    }
}

// ---------------- el/er = log2(e) * <feat[n,h,:], al/ar[h,:]> ----------------
__global__ void k_attn(const float* __restrict__ al, const float* __restrict__ ar) {
    int w = (blockIdx.x * blockDim.x + threadIdx.x) >> 5;
    int lane = threadIdx.x & 31;
    if (w >= NN) return;
    const float* f = g_feat + w * FH;
    float pl[3] = {0.f, 0.f, 0.f}, pr[3] = {0.f, 0.f, 0.f};
    #pragma unroll
    for (int r = 0; r < 6; r++) {
        int idx = lane + 32 * r;
        float v = f[idx];
        pl[r >> 1] += v * al[idx];
        pr[r >> 1] += v * ar[idx];
    }
    #pragma unroll
    for (int h = 0; h < 3; h++) {
        #pragma unroll
        for (int o = 16; o; o >>= 1) {
            pl[h] += __shfl_xor_sync(0xffffffffu, pl[h], o);
            pr[h] += __shfl_xor_sync(0xffffffffu, pr[h], o);
        }
    }
    if (lane == 0) {
        #pragma unroll
        for (int h = 0; h < 3; h++) {
            g_el[w * 3 + h] = pl[h] * LOG2E;
            g_er[w * 3 + h] = pr[h] * LOG2E;
        }
    }
}

// ---------------- per-dst softmax + aggregation + bias + lrelu + head-mean ----------------
// one warp per destination node; accumulators in registers (6 floats/lane = 192 feats)
__global__ __launch_bounds__(256) void k_agg(const float* __restrict__ b) {
    int w = (blockIdx.x * blockDim.x + threadIdx.x) >> 5;
    int lane = threadIdx.x & 31;
    if (w >= NN) return;
    int beg = g_rp[w], end = g_rp[w + 1];
    float er0 = g_er[w * 3 + 0], er1 = g_er[w * 3 + 1], er2 = g_er[w * 3 + 2];

    // pass 1: segment max per head (in log2-scaled domain)
    float m0 = -1e30f, m1 = -1e30f, m2 = -1e30f;
    for (int e = beg; e < end; e++) {
        int s = g_col[e];
        float x0 = lrelu(g_el[s * 3 + 0] + er0, 0.2f);
        float x1 = lrelu(g_el[s * 3 + 1] + er1, 0.2f);
        float x2 = lrelu(g_el[s * 3 + 2] + er2, 0.2f);
        m0 = fmaxf(m0, x0); m1 = fmaxf(m1, x1); m2 = fmaxf(m2, x2);
    }
    // pass 2: weights + weighted feature sum
    float s0 = 0.f, s1 = 0.f, s2 = 0.f;
    float a0 = 0.f, a1 = 0.f, a2 = 0.f, a3 = 0.f, a4 = 0.f, a5 = 0.f;
    for (int e = beg; e < end; e++) {
        int s = g_col[e];
        float x0 = lrelu(g_el[s * 3 + 0] + er0, 0.2f);
        float x1 = lrelu(g_el[s * 3 + 1] + er1, 0.2f);
        float x2 = lrelu(g_el[s * 3 + 2] + er2, 0.2f);
        float w0 = exp2f(x0 - m0), w1 = exp2f(x1 - m1), w2 = exp2f(x2 - m2);
        s0 += w0; s1 += w1; s2 += w2;
        const float* f = g_feat + s * FH;
        a0 += w0 * f[lane];       a1 += w0 * f[lane + 32];
        a2 += w1 * f[lane + 64];  a3 += w1 * f[lane + 96];
        a4 += w2 * f[lane + 128]; a5 += w2 * f[lane + 160];
    }
    float i0 = s0 > 0.f ? 1.f / s0 : 0.f;
    float i1 = s1 > 0.f ? 1.f / s1 : 0.f;
    float i2 = s2 > 0.f ? 1.f / s2 : 0.f;
    float v0 = lrelu(a0 * i0 + b[lane],        0.01f);
    float v1 = lrelu(a1 * i0 + b[lane + 32],   0.01f);
    float v2 = lrelu(a2 * i1 + b[lane + 64],   0.01f);
    float v3 = lrelu(a3 * i1 + b[lane + 96],   0.01f);
    float v4 = lrelu(a4 * i2 + b[lane + 128],  0.01f);
    float v5 = lrelu(a5 * i2 + b[lane + 160],  0.01f);
    g_h[w * HID + lane]      = (v0 + v2 + v4) * (1.f / 3.f);
    g_h[w * HID + lane + 32] = (v1 + v3 + v5) * (1.f / 3.f);
}

// ---------------- classifier: out = h @ Wo + bo ----------------
__global__ void k_out(const float* __restrict__ Wo, const float* __restrict__ bo,
                      float* __restrict__ out) {
    int w = (blockIdx.x * blockDim.x + threadIdx.x) >> 5;
    int lane = threadIdx.x & 31;
    if (w >= NN) return;
    float h0 = g_h[w * HID + lane];
    float h1 = g_h[w * HID + lane + 32];
    #pragma unroll
    for (int c = 0; c < 8; c++) {
        float v = h0 * Wo[lane * 8 + c] + h1 * Wo[(lane + 32) * 8 + c];
        #pragma unroll
        for (int o = 16; o; o >>= 1) v += __shfl_xor_sync(0xffffffffu, v, o);
        if (lane == 0) out[w * 8 + c] = v + bo[c];
    }
}

// ---------------- launch ----------------
extern "C" void kernel_launch(void* const* d_in, const int* in_sizes, int n_in,
                              void* d_out, int out_size) {
    const float* x   = (const float*)d_in[0];
    const int*   src = (const int*)d_in[1];
    const int*   dst = (const int*)d_in[2];
    const float *W[5], *b[5], *al[5], *ar[5];
    for (int l = 0; l < 5; l++) {
        W[l]  = (const float*)d_in[3 + 4 * l];
        b[l]  = (const float*)d_in[4 + 4 * l];
        al[l] = (const float*)d_in[5 + 4 * l];
        ar[l] = (const float*)d_in[6 + 4 * l];
    }
    const float* Wo = (const float*)d_in[23];
    const float* bo = (const float*)d_in[24];
    float* out = (float*)d_out;

    // CSR build (src/dst identical for every layer)
    k_zero<<<(NN + 255) / 256, 256>>>();
    k_hist<<<(NE + 255) / 256, 256>>>(dst);
    k_scan<<<1, 1024>>>();
    k_scatter<<<(NE + 255) / 256, 256>>>(src, dst);

    dim3 ggrid((NN + BM - 1) / BM, FH / BN);
    int wgrid = (NN * 32 + 255) / 256;
    for (int l = 0; l < 5; l++) {
        k_gemm<<<ggrid, 256>>>(l == 0 ? x : nullptr, W[l], l == 0 ? 128 : 64);
        k_attn<<<wgrid, 256>>>(al[l], ar[l]);
        k_agg<<<wgrid, 256>>>(b[l]);
    }
    k_out<<<wgrid, 256>>>(Wo, bo, out);
}

// round 4
// speedup vs baseline: 1.2313x; 1.2313x over previous
#include <cuda_runtime.h>
#include <cuda_bf16.h>
#include <math.h>
#include <stdint.h>

#define NN 50000
#define NE 800000
#define FH 192          // HEADS*HID
#define HID 64
#define LOG2E 1.4426950408889634f

// ---------------- scratch (static device globals; no allocation) ----------------
__device__ __align__(16) float g_feat[NN * FH];   // 38.4 MB
__device__ __align__(16) float g_h[NN * HID];     // 12.8 MB
__device__ __align__(16) __nv_bfloat16 g_Ahi[NN * 128];
__device__ __align__(16) __nv_bfloat16 g_Alo[NN * 128];
__device__ __align__(16) __nv_bfloat16 g_Bhi[FH * 128];   // [N=192 rows][K] row-major
__device__ __align__(16) __nv_bfloat16 g_Blo[FH * 128];
__device__ float g_el[NN * 3];
__device__ float g_er[NN * 3];
__device__ int   g_cnt[NN];
__device__ int   g_rp[NN + 1];
__device__ int   g_wp[NN];
__device__ int   g_col[NE];

__device__ __forceinline__ float lrelu(float x, float s) { return x > 0.f ? x : s * x; }

// ---------------- CSR build (sort edges by dst) ----------------
__global__ void k_zero() {
    int i = blockIdx.x * blockDim.x + threadIdx.x;
    if (i < NN) g_cnt[i] = 0;
}
__global__ void k_hist(const int* __restrict__ dst) {
    int e = blockIdx.x * blockDim.x + threadIdx.x;
    if (e < NE) atomicAdd(&g_cnt[dst[e]], 1);
}
__global__ void k_scan() {
    __shared__ int wsum[32];
    __shared__ int carry;
    int tid = threadIdx.x, lane = tid & 31, wid = tid >> 5;
    if (tid == 0) carry = 0;
    __syncthreads();
    for (int base = 0; base < NN; base += 1024) {
        int i = base + tid;
        int v = (i < NN) ? g_cnt[i] : 0;
        int x = v;
        #pragma unroll
        for (int o = 1; o < 32; o <<= 1) {
            int t = __shfl_up_sync(0xffffffffu, x, o);
            if (lane >= o) x += t;
        }
        if (lane == 31) wsum[wid] = x;
        __syncthreads();
        if (wid == 0) {
            int y = wsum[lane];
            #pragma unroll
            for (int o = 1; o < 32; o <<= 1) {
                int t = __shfl_up_sync(0xffffffffu, y, o);
                if (lane >= o) y += t;
            }
            wsum[lane] = y;
        }
        __syncthreads();
        int pre = carry + (wid ? wsum[wid - 1] : 0) + x - v;
        if (i < NN) { g_rp[i] = pre; g_wp[i] = pre; }
        __syncthreads();
        if (tid == 0) carry += wsum[31];
        __syncthreads();
    }
    if (threadIdx.x == 0) g_rp[NN] = carry;
}
__global__ void k_scatter(const int* __restrict__ src, const int* __restrict__ dst) {
    int e = blockIdx.x * blockDim.x + threadIdx.x;
    if (e < NE) {
        int p = atomicAdd(&g_wp[dst[e]], 1);
        g_col[p] = src[e];
    }
}

// ---------------- bf16 hi/lo split kernels ----------------
__global__ void k_splitA(const float* __restrict__ srcIn, int n) {
    const float* src = srcIn ? srcIn : g_h;
    int i = blockIdx.x * blockDim.x + threadIdx.x;
    if (i < n) {
        float v = src[i];
        __nv_bfloat16 h = __float2bfloat16(v);
        g_Ahi[i] = h;
        g_Alo[i] = __float2bfloat16(v - __bfloat162float(h));
    }
}
// W [K,192] fp32 -> B [192 rows x K] bf16 (transposed, K-major rows)
__global__ void k_splitW(const float* __restrict__ W, int K) {
    int i = blockIdx.x * blockDim.x + threadIdx.x;
    if (i < K * FH) {
        int k = i / FH, n = i % FH;
        float v = W[i];
        __nv_bfloat16 h = __float2bfloat16(v);
        g_Bhi[n * K + k] = h;
        g_Blo[n * K + k] = __float2bfloat16(v - __bfloat162float(h));
    }
}

// ---------------- mma.sync bf16 split GEMM: g_feat = A[.,K] @ W[K,192] ----------------
// Block tile M=128, N=96 (grid.y=2). 8 warps: 4 in M x 2 in N; warp tile 32x48.
// Split: C = Ahi*Bhi + Ahi*Blo + Alo*Bhi (fp32 accum), error ~2^-18.
__device__ __forceinline__ void mma16816(float* d, const uint32_t* a, const uint32_t* b) {
    asm volatile("mma.sync.aligned.m16n8k16.row.col.f32.bf16.bf16.f32 "
        "{%0,%1,%2,%3}, {%4,%5,%6,%7}, {%8,%9}, {%0,%1,%2,%3};"
        : "+f"(d[0]), "+f"(d[1]), "+f"(d[2]), "+f"(d[3])
        : "r"(a[0]), "r"(a[1]), "r"(a[2]), "r"(a[3]), "r"(b[0]), "r"(b[1]));
}

#define ASTR 24   // padded row stride in bf16 elems (16 data + 8 pad = 48 B)

template <int K>
__global__ __launch_bounds__(256) void k_gemm_mma(const float* __restrict__ dummy) {
    __shared__ __nv_bfloat16 As[2][128 * ASTR];  // [hi/lo]
    __shared__ __nv_bfloat16 Bs[2][96 * ASTR];
    int tid = threadIdx.x, lane = tid & 31, w = tid >> 5;
    int mw = w & 3, nw = w >> 2;
    int m0 = blockIdx.x * 128, n0 = blockIdx.y * 96;
    int g = lane >> 2, t = lane & 3;

    float d[2][6][4];
    #pragma unroll
    for (int i = 0; i < 2; i++)
        #pragma unroll
        for (int j = 0; j < 6; j++)
            #pragma unroll
            for (int q = 0; q < 4; q++) d[i][j][q] = 0.f;

    for (int k0 = 0; k0 < K; k0 += 16) {
        // A tiles: 128 rows x 32B = 256 uint4 per half; 256 threads -> 1 each
        {
            int r = tid >> 1, p = tid & 1;
            #pragma unroll
            for (int half = 0; half < 2; half++) {
                const __nv_bfloat16* src = half ? g_Alo : g_Ahi;
                uint4 v = make_uint4(0u, 0u, 0u, 0u);
                if (m0 + r < NN)
                    v = *(const uint4*)(src + (size_t)(m0 + r) * K + k0 + p * 8);
                *(uint4*)(&As[half][r * ASTR + p * 8]) = v;
            }
        }
        // B tiles: 96 rows x 32B = 192 uint4 per half
        if (tid < 192) {
            int r = tid >> 1, p = tid & 1;
            #pragma unroll
            for (int half = 0; half < 2; half++) {
                const __nv_bfloat16* src = half ? g_Blo : g_Bhi;
                uint4 v = *(const uint4*)(src + (n0 + r) * K + k0 + p * 8);
                *(uint4*)(&Bs[half][r * ASTR + p * 8]) = v;
            }
        }
        __syncthreads();

        uint32_t afr[2][2][4];
        #pragma unroll
        for (int half = 0; half < 2; half++)
            #pragma unroll
            for (int mt = 0; mt < 2; mt++) {
                const __nv_bfloat16* base = &As[half][(mw * 32 + mt * 16) * ASTR];
                afr[half][mt][0] = *(const uint32_t*)(base + g * ASTR + 2 * t);
                afr[half][mt][1] = *(const uint32_t*)(base + (g + 8) * ASTR + 2 * t);
                afr[half][mt][2] = *(const uint32_t*)(base + g * ASTR + 2 * t + 8);
                afr[half][mt][3] = *(const uint32_t*)(base + (g + 8) * ASTR + 2 * t + 8);
            }
        uint32_t bfr[2][6][2];
        #pragma unroll
        for (int half = 0; half < 2; half++)
            #pragma unroll
            for (int nt = 0; nt < 6; nt++) {
                const __nv_bfloat16* base = &Bs[half][(nw * 48 + nt * 8) * ASTR];
                bfr[half][nt][0] = *(const uint32_t*)(base + g * ASTR + 2 * t);
                bfr[half][nt][1] = *(const uint32_t*)(base + g * ASTR + 2 * t + 8);
            }
        #pragma unroll
        for (int mt = 0; mt < 2; mt++)
            #pragma unroll
            for (int nt = 0; nt < 6; nt++) {
                mma16816(d[mt][nt], afr[0][mt], bfr[0][nt]);  // hi*hi
                mma16816(d[mt][nt], afr[0][mt], bfr[1][nt]);  // hi*lo
                mma16816(d[mt][nt], afr[1][mt], bfr[0][nt]);  // lo*hi
            }
        __syncthreads();
    }

    // epilogue: d[mt][nt] regs -> (row g / g+8, cols 2t,2t+1)
    #pragma unroll
    for (int mt = 0; mt < 2; mt++) {
        int r0 = m0 + mw * 32 + mt * 16 + g;
        #pragma unroll
        for (int nt = 0; nt < 6; nt++) {
            int c = n0 + nw * 48 + nt * 8 + 2 * t;
            if (r0 < NN)
                *(float2*)&g_feat[(size_t)r0 * FH + c] = make_float2(d[mt][nt][0], d[mt][nt][1]);
            if (r0 + 8 < NN)
                *(float2*)&g_feat[(size_t)(r0 + 8) * FH + c] = make_float2(d[mt][nt][2], d[mt][nt][3]);
        }
    }
}

// ---------------- el/er = log2(e) * <feat[n,h,:], al/ar[h,:]> ----------------
__global__ void k_attn(const float* __restrict__ al, const float* __restrict__ ar) {
    int w = (blockIdx.x * blockDim.x + threadIdx.x) >> 5;
    int lane = threadIdx.x & 31;
    if (w >= NN) return;
    const float* f = g_feat + (size_t)w * FH;
    float pl[3] = {0.f, 0.f, 0.f}, pr[3] = {0.f, 0.f, 0.f};
    #pragma unroll
    for (int r = 0; r < 6; r++) {
        int idx = lane + 32 * r;
        float v = f[idx];
        pl[r >> 1] += v * al[idx];
        pr[r >> 1] += v * ar[idx];
    }
    #pragma unroll
    for (int h = 0; h < 3; h++) {
        #pragma unroll
        for (int o = 16; o; o >>= 1) {
            pl[h] += __shfl_xor_sync(0xffffffffu, pl[h], o);
            pr[h] += __shfl_xor_sync(0xffffffffu, pr[h], o);
        }
    }
    if (lane == 0) {
        #pragma unroll
        for (int h = 0; h < 3; h++) {
            g_el[w * 3 + h] = pl[h] * LOG2E;
            g_er[w * 3 + h] = pr[h] * LOG2E;
        }
    }
}

// ---------------- per-dst softmax + aggregation + bias + lrelu + head-mean ----------------
__global__ __launch_bounds__(256) void k_agg(const float* __restrict__ b) {
    int w = (blockIdx.x * blockDim.x + threadIdx.x) >> 5;
    int lane = threadIdx.x & 31;
    if (w >= NN) return;
    int beg = g_rp[w], end = g_rp[w + 1];
    float er0 = g_er[w * 3 + 0], er1 = g_er[w * 3 + 1], er2 = g_er[w * 3 + 2];

    float m0 = -1e30f, m1 = -1e30f, m2 = -1e30f;
    for (int e = beg; e < end; e++) {
        int s = g_col[e];
        float x0 = lrelu(g_el[s * 3 + 0] + er0, 0.2f);
        float x1 = lrelu(g_el[s * 3 + 1] + er1, 0.2f);
        float x2 = lrelu(g_el[s * 3 + 2] + er2, 0.2f);
        m0 = fmaxf(m0, x0); m1 = fmaxf(m1, x1); m2 = fmaxf(m2, x2);
    }
    float s0 = 0.f, s1 = 0.f, s2 = 0.f;
    float a0 = 0.f, a1 = 0.f, a2 = 0.f, a3 = 0.f, a4 = 0.f, a5 = 0.f;
    for (int e = beg; e < end; e++) {
        int s = g_col[e];
        float x0 = lrelu(g_el[s * 3 + 0] + er0, 0.2f);
        float x1 = lrelu(g_el[s * 3 + 1] + er1, 0.2f);
        float x2 = lrelu(g_el[s * 3 + 2] + er2, 0.2f);
        float w0 = exp2f(x0 - m0), w1 = exp2f(x1 - m1), w2 = exp2f(x2 - m2);
        s0 += w0; s1 += w1; s2 += w2;
        const float* f = g_feat + (size_t)s * FH;
        a0 += w0 * f[lane];       a1 += w0 * f[lane + 32];
        a2 += w1 * f[lane + 64];  a3 += w1 * f[lane + 96];
        a4 += w2 * f[lane + 128]; a5 += w2 * f[lane + 160];
    }
    float i0 = s0 > 0.f ? 1.f / s0 : 0.f;
    float i1 = s1 > 0.f ? 1.f / s1 : 0.f;
    float i2 = s2 > 0.f ? 1.f / s2 : 0.f;
    float v0 = lrelu(a0 * i0 + b[lane],        0.01f);
    float v1 = lrelu(a1 * i0 + b[lane + 32],   0.01f);
    float v2 = lrelu(a2 * i1 + b[lane + 64],   0.01f);
    float v3 = lrelu(a3 * i1 + b[lane + 96],   0.01f);
    float v4 = lrelu(a4 * i2 + b[lane + 128],  0.01f);
    float v5 = lrelu(a5 * i2 + b[lane + 160],  0.01f);
    g_h[w * HID + lane]      = (v0 + v2 + v4) * (1.f / 3.f);
    g_h[w * HID + lane + 32] = (v1 + v3 + v5) * (1.f / 3.f);
}

// ---------------- classifier ----------------
__global__ void k_out(const float* __restrict__ Wo, const float* __restrict__ bo,
                      float* __restrict__ out) {
    int w = (blockIdx.x * blockDim.x + threadIdx.x) >> 5;
    int lane = threadIdx.x & 31;
    if (w >= NN) return;
    float h0 = g_h[w * HID + lane];
    float h1 = g_h[w * HID + lane + 32];
    #pragma unroll
    for (int c = 0; c < 8; c++) {
        float v = h0 * Wo[lane * 8 + c] + h1 * Wo[(lane + 32) * 8 + c];
        #pragma unroll
        for (int o = 16; o; o >>= 1) v += __shfl_xor_sync(0xffffffffu, v, o);
        if (lane == 0) out[w * 8 + c] = v + bo[c];
    }
}

// ---------------- launch ----------------
extern "C" void kernel_launch(void* const* d_in, const int* in_sizes, int n_in,
                              void* d_out, int out_size) {
    const float* x   = (const float*)d_in[0];
    const int*   src = (const int*)d_in[1];
    const int*   dst = (const int*)d_in[2];
    const float *W[5], *b[5], *al[5], *ar[5];
    for (int l = 0; l < 5; l++) {
        W[l]  = (const float*)d_in[3 + 4 * l];
        b[l]  = (const float*)d_in[4 + 4 * l];
        al[l] = (const float*)d_in[5 + 4 * l];
        ar[l] = (const float*)d_in[6 + 4 * l];
    }
    const float* Wo = (const float*)d_in[23];
    const float* bo = (const float*)d_in[24];
    float* out = (float*)d_out;

    // CSR build
    k_zero<<<(NN + 255) / 256, 256>>>();
    k_hist<<<(NE + 255) / 256, 256>>>(dst);
    k_scan<<<1, 1024>>>();
    k_scatter<<<(NE + 255) / 256, 256>>>(src, dst);

    int wgrid = (NN * 32 + 255) / 256;
    dim3 ggrid((NN + 127) / 128, 2);
    for (int l = 0; l < 5; l++) {
        int K = (l == 0) ? 128 : 64;
        k_splitA<<<(NN * K + 255) / 256, 256>>>(l == 0 ? x : nullptr, NN * K);
        k_splitW<<<(K * FH + 255) / 256, 256>>>(W[l], K);
        if (l == 0) k_gemm_mma<128><<<ggrid, 256>>>(nullptr);
        else        k_gemm_mma<64><<<ggrid, 256>>>(nullptr);
        k_attn<<<wgrid, 256>>>(al[l], ar[l]);
        k_agg<<<wgrid, 256>>>(b[l]);
    }
    k_out<<<wgrid, 256>>>(Wo, bo, out);
}

// round 7
// speedup vs baseline: 1.4025x; 1.1390x over previous
#include <cuda_runtime.h>
#include <cuda_bf16.h>
#include <math.h>
#include <stdint.h>

#define NN 50000
#define NE 800000
#define FH 192          // HEADS*HID
#define HID 64
#define LOG2E 1.4426950408889634f

// ---------------- scratch (static device globals; no allocation) ----------------
__device__ __align__(16) float g_feat[NN * FH];   // 38.4 MB
__device__ __align__(16) float g_h[NN * HID];
__device__ __align__(16) __nv_bfloat16 g_Ahi[NN * 128];
__device__ __align__(16) __nv_bfloat16 g_Alo[NN * 128];
// all 5 layers' W, transposed [N=192][K] bf16: layer0 K=128, rest K=64
#define BW_TOT (192*128 + 4*192*64)
__device__ __align__(16) __nv_bfloat16 g_Bhi5[BW_TOT];
__device__ __align__(16) __nv_bfloat16 g_Blo5[BW_TOT];
__device__ __align__(16) float4 g_el4[NN];
__device__ __align__(16) float4 g_er4[NN];
__device__ int   g_cnt[NN];
__device__ int   g_rp[NN + 1];
__device__ int   g_wp[NN];
__device__ int   g_col[NE];
__device__ int   g_bsum[64];

__device__ __forceinline__ float lrelu(float x, float s) { return x > 0.f ? x : s * x; }

// ---------------- CSR build ----------------
__global__ void k_zero() {
    int i = blockIdx.x * blockDim.x + threadIdx.x;
    if (i < NN) g_cnt[i] = 0;
}
__global__ void k_hist(const int* __restrict__ dst) {
    int e = blockIdx.x * blockDim.x + threadIdx.x;
    if (e < NE) atomicAdd(&g_cnt[dst[e]], 1);
}
// multi-block scan: phase A = per-block exclusive scan + block sums
__global__ __launch_bounds__(1024) void k_scanA() {
    __shared__ int wsum[32];
    int tid = threadIdx.x, lane = tid & 31, wid = tid >> 5;
    int i = blockIdx.x * 1024 + tid;
    int v = (i < NN) ? g_cnt[i] : 0;
    int x = v;
    #pragma unroll
    for (int o = 1; o < 32; o <<= 1) {
        int t = __shfl_up_sync(0xffffffffu, x, o);
        if (lane >= o) x += t;
    }
    if (lane == 31) wsum[wid] = x;
    __syncthreads();
    if (wid == 0) {
        int y = wsum[lane];
        #pragma unroll
        for (int o = 1; o < 32; o <<= 1) {
            int t = __shfl_up_sync(0xffffffffu, y, o);
            if (lane >= o) y += t;
        }
        wsum[lane] = y;
    }
    __syncthreads();
    int pre = (wid ? wsum[wid - 1] : 0) + x - v;  // exclusive within block
    if (i < NN) g_rp[i] = pre;
    if (tid == 1023) g_bsum[blockIdx.x] = pre + v;
}
// phase B: add block-prefix offsets
__global__ __launch_bounds__(1024) void k_scanB(int nblk) {
    __shared__ int sb[64];
    int tid = threadIdx.x;
    if (tid < nblk) sb[tid] = g_bsum[tid];
    __syncthreads();
    int off = 0;
    for (int j = 0; j < (int)blockIdx.x; j++) off += sb[j];
    int i = blockIdx.x * 1024 + tid;
    if (i < NN) {
        int v = g_rp[i] + off;
        g_rp[i] = v;
        g_wp[i] = v;
    }
    if (blockIdx.x == gridDim.x - 1 && tid == 0) {
        int tot = 0;
        for (int j = 0; j < nblk; j++) tot += sb[j];
        g_rp[NN] = tot;
    }
}
__global__ void k_scatter(const int* __restrict__ src, const int* __restrict__ dst) {
    int e = blockIdx.x * blockDim.x + threadIdx.x;
    if (e < NE) {
        int p = atomicAdd(&g_wp[dst[e]], 1);
        g_col[p] = src[e];
    }
}

// ---------------- bf16 hi/lo splits ----------------
__global__ void k_splitA(const float* __restrict__ src, int n) {
    int i = blockIdx.x * blockDim.x + threadIdx.x;
    if (i < n) {
        float v = src[i];
        __nv_bfloat16 h = __float2bfloat16(v);
        g_Ahi[i] = h;
        g_Alo[i] = __float2bfloat16(v - __bfloat162float(h));
    }
}
// all 5 weights at once; W[l] is [K,192] fp32 -> [192][K] bf16
__global__ void k_splitW_all(const float* __restrict__ W0, const float* __restrict__ W1,
                             const float* __restrict__ W2, const float* __restrict__ W3,
                             const float* __restrict__ W4) {
    int i = blockIdx.x * blockDim.x + threadIdx.x;
    if (i >= BW_TOT) return;
    int l, j, K, off;
    if (i < 192 * 128) { l = 0; j = i; K = 128; off = 0; }
    else {
        int r = i - 192 * 128;
        l = 1 + r / (192 * 64);
        j = r % (192 * 64);
        K = 64;
        off = 192 * 128 + (l - 1) * 192 * 64;
    }
    const float* W = (l == 0) ? W0 : (l == 1) ? W1 : (l == 2) ? W2 : (l == 3) ? W3 : W4;
    int k = j / FH, n = j % FH;
    float v = W[j];
    __nv_bfloat16 h = __float2bfloat16(v);
    g_Bhi5[off + n * K + k] = h;
    g_Blo5[off + n * K + k] = __float2bfloat16(v - __bfloat162float(h));
}

// ---------------- mma.sync bf16 split GEMM ----------------
__device__ __forceinline__ void mma16816(float* d, const uint32_t* a, const uint32_t* b) {
    asm volatile("mma.sync.aligned.m16n8k16.row.col.f32.bf16.bf16.f32 "
        "{%0,%1,%2,%3}, {%4,%5,%6,%7}, {%8,%9}, {%0,%1,%2,%3};"
        : "+f"(d[0]), "+f"(d[1]), "+f"(d[2]), "+f"(d[3])
        : "r"(a[0]), "r"(a[1]), "r"(a[2]), "r"(a[3]), "r"(b[0]), "r"(b[1]));
}
#define ASTR 24

template <int K>
__global__ __launch_bounds__(256) void k_gemm_mma(int boff) {
    __shared__ __nv_bfloat16 As[2][128 * ASTR];
    __shared__ __nv_bfloat16 Bs[2][96 * ASTR];
    int tid = threadIdx.x, lane = tid & 31, w = tid >> 5;
    int mw = w & 3, nw = w >> 2;
    int m0 = blockIdx.x * 128, n0 = blockIdx.y * 96;
    int g = lane >> 2, t = lane & 3;

    float d[2][6][4];
    #pragma unroll
    for (int i = 0; i < 2; i++)
        #pragma unroll
        for (int j = 0; j < 6; j++)
            #pragma unroll
            for (int q = 0; q < 4; q++) d[i][j][q] = 0.f;

    for (int k0 = 0; k0 < K; k0 += 16) {
        {
            int r = tid >> 1, p = tid & 1;
            #pragma unroll
            for (int half = 0; half < 2; half++) {
                const __nv_bfloat16* src = half ? g_Alo : g_Ahi;
                uint4 v = make_uint4(0u, 0u, 0u, 0u);
                if (m0 + r < NN)
                    v = *(const uint4*)(src + (size_t)(m0 + r) * K + k0 + p * 8);
                *(uint4*)(&As[half][r * ASTR + p * 8]) = v;
            }
        }
        if (tid < 192) {
            int r = tid >> 1, p = tid & 1;
            #pragma unroll
            for (int half = 0; half < 2; half++) {
                const __nv_bfloat16* src = (half ? g_Blo5 : g_Bhi5) + boff;
                uint4 v = *(const uint4*)(src + (n0 + r) * K + k0 + p * 8);
                *(uint4*)(&Bs[half][r * ASTR + p * 8]) = v;
            }
        }
        __syncthreads();

        uint32_t afr[2][2][4];
        #pragma unroll
        for (int half = 0; half < 2; half++)
            #pragma unroll
            for (int mt = 0; mt < 2; mt++) {
                const __nv_bfloat16* base = &As[half][(mw * 32 + mt * 16) * ASTR];
                afr[half][mt][0] = *(const uint32_t*)(base + g * ASTR + 2 * t);
                afr[half][mt][1] = *(const uint32_t*)(base + (g + 8) * ASTR + 2 * t);
                afr[half][mt][2] = *(const uint32_t*)(base + g * ASTR + 2 * t + 8);
                afr[half][mt][3] = *(const uint32_t*)(base + (g + 8) * ASTR + 2 * t + 8);
            }
        uint32_t bfr[2][6][2];
        #pragma unroll
        for (int half = 0; half < 2; half++)
            #pragma unroll
            for (int nt = 0; nt < 6; nt++) {
                const __nv_bfloat16* base = &Bs[half][(nw * 48 + nt * 8) * ASTR];
                bfr[half][nt][0] = *(const uint32_t*)(base + g * ASTR + 2 * t);
                bfr[half][nt][1] = *(const uint32_t*)(base + g * ASTR + 2 * t + 8);
            }
        #pragma unroll
        for (int mt = 0; mt < 2; mt++)
            #pragma unroll
            for (int nt = 0; nt < 6; nt++) {
                mma16816(d[mt][nt], afr[0][mt], bfr[0][nt]);
                mma16816(d[mt][nt], afr[0][mt], bfr[1][nt]);
                mma16816(d[mt][nt], afr[1][mt], bfr[0][nt]);
            }
        __syncthreads();
    }

    #pragma unroll
    for (int mt = 0; mt < 2; mt++) {
        int r0 = m0 + mw * 32 + mt * 16 + g;
        #pragma unroll
        for (int nt = 0; nt < 6; nt++) {
            int c = n0 + nw * 48 + nt * 8 + 2 * t;
            if (r0 < NN)
                *(float2*)&g_feat[(size_t)r0 * FH + c] = make_float2(d[mt][nt][0], d[mt][nt][1]);
            if (r0 + 8 < NN)
                *(float2*)&g_feat[(size_t)(r0 + 8) * FH + c] = make_float2(d[mt][nt][2], d[mt][nt][3]);
        }
    }
}

// ---------------- attention logits (float2 loads, float4 output) ----------------
__global__ void k_attn(const float* __restrict__ al, const float* __restrict__ ar) {
    int w = (blockIdx.x * blockDim.x + threadIdx.x) >> 5;
    int lane = threadIdx.x & 31;
    if (w >= NN) return;
    const float2* f2 = (const float2*)(g_feat + (size_t)w * FH);
    float pl[3], pr[3];
    #pragma unroll
    for (int h = 0; h < 3; h++) {
        float2 v = f2[h * 32 + lane];
        float2 a = *(const float2*)(al + h * 64 + 2 * lane);
        float2 r = *(const float2*)(ar + h * 64 + 2 * lane);
        pl[h] = v.x * a.x + v.y * a.y;
        pr[h] = v.x * r.x + v.y * r.y;
    }
    #pragma unroll
    for (int h = 0; h < 3; h++) {
        #pragma unroll
        for (int o = 16; o; o >>= 1) {
            pl[h] += __shfl_xor_sync(0xffffffffu, pl[h], o);
            pr[h] += __shfl_xor_sync(0xffffffffu, pr[h], o);
        }
    }
    if (lane == 0) {
        g_el4[w] = make_float4(pl[0] * LOG2E, pl[1] * LOG2E, pl[2] * LOG2E, 0.f);
        g_er4[w] = make_float4(pr[0] * LOG2E, pr[1] * LOG2E, pr[2] * LOG2E, 0.f);
    }
}

// ---------------- single-pass online-softmax aggregation (+ fused split / classifier) ----------------
__global__ __launch_bounds__(256) void k_agg(const float* __restrict__ b,
                                             const float* __restrict__ Wo,
                                             const float* __restrict__ bo,
                                             float* __restrict__ out) {
    int w = (blockIdx.x * blockDim.x + threadIdx.x) >> 5;
    int lane = threadIdx.x & 31;
    if (w >= NN) return;
    int beg = g_rp[w], end = g_rp[w + 1];
    float4 er = g_er4[w];

    float m0 = -1e30f, m1 = -1e30f, m2 = -1e30f;
    float s0 = 0.f, s1 = 0.f, s2 = 0.f;
    float2 a0 = {0.f, 0.f}, a1 = {0.f, 0.f}, a2 = {0.f, 0.f};

    for (int e = beg; e < end; e++) {
        int s = g_col[e];
        float4 el = g_el4[s];
        float x0 = lrelu(el.x + er.x, 0.2f);
        float x1 = lrelu(el.y + er.y, 0.2f);
        float x2 = lrelu(el.z + er.z, 0.2f);
        if (x0 > m0) { float sc = exp2f(m0 - x0); s0 *= sc; a0.x *= sc; a0.y *= sc; m0 = x0; }
        if (x1 > m1) { float sc = exp2f(m1 - x1); s1 *= sc; a1.x *= sc; a1.y *= sc; m1 = x1; }
        if (x2 > m2) { float sc = exp2f(m2 - x2); s2 *= sc; a2.x *= sc; a2.y *= sc; m2 = x2; }
        float w0 = exp2f(x0 - m0), w1 = exp2f(x1 - m1), w2 = exp2f(x2 - m2);
        s0 += w0; s1 += w1; s2 += w2;
        const float2* f2 = (const float2*)(g_feat + (size_t)s * FH);
        float2 v0 = f2[lane], v1 = f2[lane + 32], v2 = f2[lane + 64];
        a0.x += w0 * v0.x; a0.y += w0 * v0.y;
        a1.x += w1 * v1.x; a1.y += w1 * v1.y;
        a2.x += w2 * v2.x; a2.y += w2 * v2.y;
    }
    float i0 = s0 > 0.f ? 1.f / s0 : 0.f;
    float i1 = s1 > 0.f ? 1.f / s1 : 0.f;
    float i2 = s2 > 0.f ? 1.f / s2 : 0.f;
    float2 b0 = *(const float2*)(b + 2 * lane);
    float2 b1 = *(const float2*)(b + 64 + 2 * lane);
    float2 b2 = *(const float2*)(b + 128 + 2 * lane);
    float v0x = lrelu(a0.x * i0 + b0.x, 0.01f), v0y = lrelu(a0.y * i0 + b0.y, 0.01f);
    float v1x = lrelu(a1.x * i1 + b1.x, 0.01f), v1y = lrelu(a1.y * i1 + b1.y, 0.01f);
    float v2x = lrelu(a2.x * i2 + b2.x, 0.01f), v2y = lrelu(a2.y * i2 + b2.y, 0.01f);
    float rx = (v0x + v1x + v2x) * (1.f / 3.f);
    float ry = (v0y + v1y + v2y) * (1.f / 3.f);

    if (Wo) {
        // fused classifier: out[w] = h @ Wo + bo; lane holds feats 2L,2L+1
        #pragma unroll
        for (int c = 0; c < 8; c++) {
            float v = rx * Wo[(2 * lane) * 8 + c] + ry * Wo[(2 * lane + 1) * 8 + c];
            #pragma unroll
            for (int o = 16; o; o >>= 1) v += __shfl_xor_sync(0xffffffffu, v, o);
            if (lane == 0) out[w * 8 + c] = v + bo[c];
        }
    } else {
        // write next layer's bf16 hi/lo split directly (K=64 layout)
        __nv_bfloat16 hx = __float2bfloat16(rx);
        __nv_bfloat16 hy = __float2bfloat16(ry);
        __nv_bfloat16 lx = __float2bfloat16(rx - __bfloat162float(hx));
        __nv_bfloat16 ly = __float2bfloat16(ry - __bfloat162float(hy));
        ((__nv_bfloat162*)g_Ahi)[w * 32 + lane] = __nv_bfloat162(hx, hy);
        ((__nv_bfloat162*)g_Alo)[w * 32 + lane] = __nv_bfloat162(lx, ly);
    }
}

// ---------------- launch ----------------
extern "C" void kernel_launch(void* const* d_in, const int* in_sizes, int n_in,
                              void* d_out, int out_size) {
    const float* x   = (const float*)d_in[0];
    const int*   src = (const int*)d_in[1];
    const int*   dst = (const int*)d_in[2];
    const float *W[5], *b[5], *al[5], *ar[5];
    for (int l = 0; l < 5; l++) {
        W[l]  = (const float*)d_in[3 + 4 * l];
        b[l]  = (const float*)d_in[4 + 4 * l];
        al[l] = (const float*)d_in[5 + 4 * l];
        ar[l] = (const float*)d_in[6 + 4 * l];
    }
    const float* Wo = (const float*)d_in[23];
    const float* bo = (const float*)d_in[24];
    float* out = (float*)d_out;

    // CSR build
    int nblk = (NN + 1023) / 1024;  // 49
    k_zero<<<(NN + 255) / 256, 256>>>();
    k_hist<<<(NE + 255) / 256, 256>>>(dst);
    k_scanA<<<nblk, 1024>>>();
    k_scanB<<<nblk, 1024>>>(nblk);
    k_scatter<<<(NE + 255) / 256, 256>>>(src, dst);

    // weight splits (all layers) + input split
    k_splitW_all<<<(BW_TOT + 255) / 256, 256>>>(W[0], W[1], W[2], W[3], W[4]);
    k_splitA<<<(NN * 128 + 255) / 256, 256>>>(x, NN * 128);

    int wgrid = (NN * 32 + 255) / 256;
    dim3 ggrid((NN + 127) / 128, 2);
    for (int l = 0; l < 5; l++) {
        int boff = (l == 0) ? 0 : 192 * 128 + (l - 1) * 192 * 64;
        if (l == 0) k_gemm_mma<128><<<ggrid, 256>>>(boff);
        else        k_gemm_mma<64><<<ggrid, 256>>>(boff);
        k_attn<<<wgrid, 256>>>(al[l], ar[l]);
        if (l == 4) k_agg<<<wgrid, 256>>>(b[l], Wo, bo, out);
        else        k_agg<<<wgrid, 256>>>(b[l], nullptr, nullptr, nullptr);
    }
}